// round 5
// baseline (speedup 1.0000x reference)
#include <cuda_runtime.h>
#include <cstdint>
#include <cstddef>

// ---------------------------------------------------------------------------
// MSReversibleRefine: B=4, DIM=64, HP=32, NHEAD=8, WS=16, H=W=128
//   d_in: 0 reused_attn (256,8,256,256) | 1 refined_lms (4,64,128,128)
//         2 hp_in (4,32,128,128) | 3 ra_w1 (8,8,1,3) | 4 ra_w2 (8,8,1,1)
//         5 ra_b2 (8) | 6 dw_w (64,1,3,3) | 7 dw_b (64) | 8 pw_w (64,64,1,1)
//         9 pw_b (64) | 10 fuse_w (64,96,3,3) | 11 fuse_b (64)
//   d_out: attn (134217728 f32) ++ out (4194304 f32)
// ---------------------------------------------------------------------------
#define ATTN_ELEMS 134217728LL
#define FULLM 0xffffffffu

// scratch (static device globals: the sanctioned no-alloc workaround)
__device__ __align__(128) float g_refl[4 * 64 * 128 * 128]; // reflashed
__device__ __align__(128) float g_t   [4 * 64 * 128 * 128]; // dw+relu
__device__ __align__(128) float g_res [4 * 64 * 128 * 128]; // pw + reflashed
__device__ __align__(128) float g_fw  [96 * 9 * 64];        // fuse w: [c][tap][o]
__device__ __align__(128) float g_eff [200];                // [h][24 coeffs + bias]

// ---------------------------------------------------------------------------
// prep: eff[h][ci][dx] = sum_co w2[h,co]*w1[co,ci,dx];  transpose fuse weights
// ---------------------------------------------------------------------------
__global__ void prep_kernel(const float* __restrict__ w1, const float* __restrict__ w2,
                            const float* __restrict__ b2, const float* __restrict__ fw)
{
    int t = blockIdx.x * 256 + threadIdx.x;
    if (t < 200) {
        int h = t / 25, k = t % 25;
        if (k < 24) {
            int ci = k / 3, dx = k % 3;
            float s = 0.f;
            #pragma unroll
            for (int co = 0; co < 8; co++)
                s += w2[h * 8 + co] * w1[(co * 8 + ci) * 3 + dx];
            g_eff[h * 25 + k] = s;
        } else {
            g_eff[h * 25 + 24] = b2[h];
        }
    }
    if (t < 96 * 9 * 64) {
        int o = t & 63;
        int r = t >> 6;
        int tap = r % 9;
        int c = r / 9;
        g_fw[t] = fw[(o * 96 + c) * 9 + tap];
    }
}

// ---------------------------------------------------------------------------
// attn kernel: one block per window (256 blocks), warp = head.
// Computes eff-conv -> relu -> softmax, writes attn, and fuses the einsum
// (x_out[h,d,n] = sum_m attn[m,n]*x[h,d,m]) accumulating in registers,
// finally scattering reflashed into g_refl.
// ---------------------------------------------------------------------------
__global__ __launch_bounds__(256, 2)
void attn_kernel(const float* __restrict__ reused,
                 const float* __restrict__ refined,
                 float* __restrict__ attn_out)
{
    extern __shared__ float sm[];
    float* xw  = sm;                       // 64*256 window pixels [ch][m]
    float* buf = sm + 64 * 256;            // 2 * 8 * 256 row double buffer
    float* eff = sm + 64 * 256 + 2 * 2048; // 200

    const int bw   = blockIdx.x;
    const int tid  = threadIdx.x;
    const int h    = tid >> 5;
    const int lane = tid & 31;

    const int b  = bw >> 6;
    const int g1 = (bw >> 3) & 7;
    const int g2 = bw & 7;

    for (int i = tid; i < 200; i += 256) eff[i] = g_eff[i];

    // load window pixels: xw[ch*256 + m] = refined[b, ch, (m>>4)*8+g1, (m&15)*8+g2]
    {
        const float* rbase = refined + (size_t)b * 64 * 16384;
        for (int i = tid; i < 16384; i += 256) {
            int ch = i >> 8, m = i & 255;
            int y = ((m >> 4) << 3) + g1;
            int x = ((m & 15) << 3) + g2;
            xw[i] = rbase[ch * 16384 + y * 128 + x];
        }
    }

    float acc[8][8];
    #pragma unroll
    for (int d = 0; d < 8; d++)
        #pragma unroll
        for (int i = 0; i < 8; i++) acc[d][i] = 0.f;

    const size_t rowbase = (size_t)(bw * 8 + h) * 65536; // + m*256 per row

    // preload row m=0 (warp h loads channel h)
    {
        const float4* rl = (const float4*)(reused + rowbase);
        float4 la = __ldg(rl + lane);
        float4 lb = __ldg(rl + 32 + lane);
        float4* bp = (float4*)(buf + h * 256);
        int c0 = lane,      s0 = c0 ^ ((c0 >> 3) & 7);
        int c1 = 32 + lane, s1 = c1 ^ ((c1 >> 3) & 7);
        bp[s0] = la;
        bp[s1] = lb;
    }
    __syncthreads();

    const float bias = eff[h * 25 + 24];
    const int cA = 2 * lane;
    const int cB = cA + 1;
    const int sA = cA ^ ((cA >> 3) & 7);
    const int sB = cB ^ ((cB >> 3) & 7);

    #pragma unroll 1
    for (int m = 0; m < 256; m++) {
        const int ph = m & 1;
        const bool pre = (m + 1 < 256);
        float4 la, lb;
        if (pre) {
            const float4* rl = (const float4*)(reused + rowbase + (size_t)(m + 1) * 256);
            la = __ldg(rl + lane);
            lb = __ldg(rl + 32 + lane);
        }

        // effective 8x8x3 stencil
        float a[8];
        #pragma unroll
        for (int i = 0; i < 8; i++) a[i] = bias;

        const float4* rp = (const float4*)(buf + ph * 2048);
        #pragma unroll
        for (int c = 0; c < 8; c++) {
            float4 va = rp[c * 64 + sA];
            float4 vb = rp[c * 64 + sB];
            float v[8] = {va.x, va.y, va.z, va.w, vb.x, vb.y, vb.z, vb.w};
            float lh = __shfl_up_sync(FULLM, v[7], 1);
            float rh = __shfl_down_sync(FULLM, v[0], 1);
            if (lane == 0)  lh = 0.f;
            if (lane == 31) rh = 0.f;
            float e0 = eff[h * 25 + c * 3 + 0];
            float e1 = eff[h * 25 + c * 3 + 1];
            float e2 = eff[h * 25 + c * 3 + 2];
            #pragma unroll
            for (int i = 0; i < 8; i++) {
                float L = (i == 0) ? lh : v[i - 1];
                float R = (i == 7) ? rh : v[i + 1];
                a[i] = fmaf(e0, L, a[i]);
                a[i] = fmaf(e1, v[i], a[i]);
                a[i] = fmaf(e2, R, a[i]);
            }
        }

        // relu + warp softmax over 256 (8 per lane)
        float mx = 0.f;
        #pragma unroll
        for (int i = 0; i < 8; i++) { a[i] = fmaxf(a[i], 0.f); mx = fmaxf(mx, a[i]); }
        #pragma unroll
        for (int o = 16; o; o >>= 1) mx = fmaxf(mx, __shfl_xor_sync(FULLM, mx, o));
        float sum = 0.f;
        #pragma unroll
        for (int i = 0; i < 8; i++) { a[i] = __expf(a[i] - mx); sum += a[i]; }
        #pragma unroll
        for (int o = 16; o; o >>= 1) sum += __shfl_xor_sync(FULLM, sum, o);
        float inv = __fdividef(1.f, sum);
        #pragma unroll
        for (int i = 0; i < 8; i++) a[i] *= inv;

        // store attn row (two STG.128 per lane, warp-coalesced)
        {
            float4* op = (float4*)(attn_out + rowbase + (size_t)m * 256);
            op[2 * lane]     = make_float4(a[0], a[1], a[2], a[3]);
            op[2 * lane + 1] = make_float4(a[4], a[5], a[6], a[7]);
        }

        // fused einsum accumulate: acc[d][i] += a[i] * x[h,d,m]
        {
            const float* xcol = xw + (h * 8) * 256 + m;
            #pragma unroll
            for (int d = 0; d < 8; d++) {
                float xv = xcol[d * 256]; // broadcast LDS
                #pragma unroll
                for (int i = 0; i < 8; i++) acc[d][i] = fmaf(a[i], xv, acc[d][i]);
            }
        }

        // stage prefetched row
        if (pre) {
            float4* bp = (float4*)(buf + (ph ^ 1) * 2048 + h * 256);
            int c0 = lane,      s0 = c0 ^ ((c0 >> 3) & 7);
            int c1 = 32 + lane, s1 = c1 ^ ((c1 >> 3) & 7);
            bp[s0] = la;
            bp[s1] = lb;
        }
        __syncthreads();
    }

    // scatter reflashed: g_refl[b, h*8+d, (n>>4)*8+g1, (n&15)*8+g2]
    {
        float* gout = g_refl + ((size_t)b * 64 + h * 8) * 16384;
        #pragma unroll
        for (int d = 0; d < 8; d++) {
            #pragma unroll
            for (int i = 0; i < 8; i++) {
                int n = lane * 8 + i;
                int y = ((n >> 4) << 3) + g1;
                int x = ((n & 15) << 3) + g2;
                gout[d * 16384 + y * 128 + x] = acc[d][i];
            }
        }
    }
}

// ---------------------------------------------------------------------------
// depthwise 3x3 + bias + relu : g_refl -> g_t
// ---------------------------------------------------------------------------
__global__ void dw_kernel(const float* __restrict__ dww, const float* __restrict__ dwb)
{
    int x  = blockIdx.x * 32 + threadIdx.x;
    int y  = blockIdx.y * 8 + threadIdx.y;
    int cz = blockIdx.z;           // b*64 + ch
    int ch = cz & 63;
    const float* in = g_refl + (size_t)cz * 16384;
    const float* w  = dww + ch * 9;
    float s = dwb[ch];
    #pragma unroll
    for (int dy = 0; dy < 3; dy++) {
        int yy = y + dy - 1;
        if ((unsigned)yy >= 128u) continue;
        #pragma unroll
        for (int dx = 0; dx < 3; dx++) {
            int xx = x + dx - 1;
            if ((unsigned)xx >= 128u) continue;
            s = fmaf(w[dy * 3 + dx], in[yy * 128 + xx], s);
        }
    }
    g_t[(size_t)cz * 16384 + y * 128 + x] = fmaxf(s, 0.f);
}

// ---------------------------------------------------------------------------
// pointwise 64->64 + bias + residual : g_res = pw(g_t) + g_refl
// ---------------------------------------------------------------------------
__global__ __launch_bounds__(256)
void pw_kernel(const float* __restrict__ pww, const float* __restrict__ pwb)
{
    __shared__ float w[4096];
    __shared__ float bsh[64];
    int t = threadIdx.x;
    for (int i = t; i < 4096; i += 256) w[i] = pww[i];
    if (t < 64) bsh[t] = pwb[t];
    __syncthreads();

    size_t p   = (size_t)blockIdx.x * 256 + t; // 0..65535
    int b      = (int)(p >> 14);
    int pix    = (int)(p & 16383);
    const float* tin = g_t   + (size_t)b * 64 * 16384 + pix;
    const float* rin = g_refl + (size_t)b * 64 * 16384 + pix;
    float*       ro  = g_res + (size_t)b * 64 * 16384 + pix;

    float in[64];
    #pragma unroll
    for (int c = 0; c < 64; c++) in[c] = tin[c * 16384];

    #pragma unroll 4
    for (int o = 0; o < 64; o++) {
        float s = bsh[o];
        const float4* wr = (const float4*)(w + o * 64);
        #pragma unroll
        for (int c4 = 0; c4 < 16; c4++) {
            float4 ww = wr[c4];
            s = fmaf(ww.x, in[4 * c4 + 0], s);
            s = fmaf(ww.y, in[4 * c4 + 1], s);
            s = fmaf(ww.z, in[4 * c4 + 2], s);
            s = fmaf(ww.w, in[4 * c4 + 3], s);
        }
        ro[o * 16384] = s + rin[o * 16384];
    }
}

// ---------------------------------------------------------------------------
// fuse conv 3x3 (96 -> 64) + bias, then out = g_refl * conv
// block = 16x16 pixel tile, thread = pixel, acc[64] in regs, channels in
// chunks of 8 (tile + o-contiguous weights staged in static smem).
// ---------------------------------------------------------------------------
__global__ __launch_bounds__(256, 2)
void fuse_kernel(const float* __restrict__ hp, const float* __restrict__ fb,
                 float* __restrict__ out)
{
    __shared__ float tile[8 * 324];   // 8 ch x 18x18
    __shared__ float wsh[8 * 9 * 64]; // 8 ch x 9 taps x 64 o

    int b   = blockIdx.z;
    int tyb = blockIdx.y * 16;
    int txb = blockIdx.x * 16;
    int tid = threadIdx.x;
    int tx  = tid & 15, ty = tid >> 4;

    float acc[64];
    #pragma unroll
    for (int o = 0; o < 64; o++) acc[o] = 0.f;

    for (int cc = 0; cc < 96; cc += 8) {
        __syncthreads();
        // stage 8-channel input tile with zero-pad halo
        for (int i = tid; i < 8 * 324; i += 256) {
            int c = i / 324, r = i % 324;
            int iy = r / 18, ix = r % 18;
            int y = tyb + iy - 1, x = txb + ix - 1;
            float v = 0.f;
            if ((unsigned)y < 128u && (unsigned)x < 128u) {
                int ch = cc + c;
                v = (ch < 64)
                    ? g_res[((size_t)b * 64 + ch) * 16384 + y * 128 + x]
                    : hp  [((size_t)b * 32 + (ch - 64)) * 16384 + y * 128 + x];
            }
            tile[i] = v;
        }
        // stage weights (already o-contiguous)
        for (int i = tid; i < 8 * 576; i += 256) wsh[i] = g_fw[cc * 576 + i];
        __syncthreads();

        #pragma unroll 1
        for (int c = 0; c < 8; c++) {
            #pragma unroll
            for (int tap = 0; tap < 9; tap++) {
                int dy = tap / 3, dx = tap % 3;
                float v = tile[c * 324 + (ty + dy) * 18 + (tx + dx)];
                const float4* wp = (const float4*)(wsh + (c * 9 + tap) * 64);
                #pragma unroll
                for (int o4 = 0; o4 < 16; o4++) {
                    float4 w4 = wp[o4]; // broadcast LDS.128
                    acc[4 * o4 + 0] = fmaf(w4.x, v, acc[4 * o4 + 0]);
                    acc[4 * o4 + 1] = fmaf(w4.y, v, acc[4 * o4 + 1]);
                    acc[4 * o4 + 2] = fmaf(w4.z, v, acc[4 * o4 + 2]);
                    acc[4 * o4 + 3] = fmaf(w4.w, v, acc[4 * o4 + 3]);
                }
            }
        }
    }

    int y = tyb + ty, x = txb + tx;
    size_t pix = (size_t)y * 128 + x;
    #pragma unroll 4
    for (int o = 0; o < 64; o++) {
        size_t idx = ((size_t)b * 64 + o) * 16384 + pix;
        out[idx] = g_refl[idx] * (acc[o] + fb[o]);
    }
}

// ---------------------------------------------------------------------------
extern "C" void kernel_launch(void* const* d_in, const int* in_sizes, int n_in,
                              void* d_out, int out_size)
{
    const float* reused  = (const float*)d_in[0];
    const float* refined = (const float*)d_in[1];
    const float* hp      = (const float*)d_in[2];
    const float* ra_w1   = (const float*)d_in[3];
    const float* ra_w2   = (const float*)d_in[4];
    const float* ra_b2   = (const float*)d_in[5];
    const float* dw_w    = (const float*)d_in[6];
    const float* dw_b    = (const float*)d_in[7];
    const float* pw_w    = (const float*)d_in[8];
    const float* pw_b    = (const float*)d_in[9];
    const float* fuse_w  = (const float*)d_in[10];
    const float* fuse_b  = (const float*)d_in[11];

    float* attn_out = (float*)d_out;
    float* out_out  = (float*)d_out + ATTN_ELEMS;

    // 1. weight prep
    prep_kernel<<<216, 256>>>(ra_w1, ra_w2, ra_b2, fuse_w);

    // 2. fused attn-conv + softmax + einsum
    const int smem = (64 * 256 + 2 * 2048 + 200) * (int)sizeof(float); // 82720
    cudaFuncSetAttribute(attn_kernel, cudaFuncAttributeMaxDynamicSharedMemorySize, smem);
    attn_kernel<<<256, 256, smem>>>(reused, refined, attn_out);

    // 3. depthwise + relu
    dw_kernel<<<dim3(4, 16, 256), dim3(32, 8)>>>(dw_w, dw_b);

    // 4. pointwise + residual
    pw_kernel<<<256, 256>>>(pw_w, pw_b);

    // 5. fuse conv + gate
    fuse_kernel<<<dim3(8, 8, 4), 256>>>(hp, fuse_b, out_out);
}